// round 1
// baseline (speedup 1.0000x reference)
#include <cuda_runtime.h>
#include <cstdint>
#include <cstddef>

// Problem constants
#define DMODEL 1024
#define SEQ    4096
#define BATCH  4
#define NHEAD  16
#define DK     64
#define M_TOTAL (BATCH * SEQ)   // 16384
#define BH      (BATCH * NHEAD) // 64
#define NCH     8               // s-chunks for KV partial reduction

// ---------------- scratch (static device globals; no allocation) ----------------
__device__ float g_Q[(size_t)M_TOTAL * DMODEL];
__device__ float g_K[(size_t)M_TOTAL * DMODEL];
__device__ float g_V[(size_t)M_TOTAL * DMODEL];
__device__ float g_attn[(size_t)M_TOTAL * DMODEL];
__device__ float g_pKV[(size_t)NCH * BH * DK * DK];
__device__ float g_pKsum[(size_t)NCH * BH * DK];
__device__ float g_KV[(size_t)BH * DK * DK];
__device__ float g_Ksum[(size_t)BH * DK];

// ---------------- packed f32x2 helpers (sm_103a FFMA2 path) ----------------
__device__ __forceinline__ unsigned long long pack2(float x, float y) {
    unsigned long long r;
    asm("mov.b64 %0, {%1, %2};" : "=l"(r) : "f"(x), "f"(y));
    return r;
}
__device__ __forceinline__ void unpack2(unsigned long long v, float& x, float& y) {
    asm("mov.b64 {%0, %1}, %2;" : "=f"(x), "=f"(y) : "l"(v));
}
__device__ __forceinline__ void ffma2(unsigned long long& d,
                                      unsigned long long a,
                                      unsigned long long b) {
    asm("fma.rn.f32x2 %0, %1, %2, %0;" : "+l"(d) : "l"(a), "l"(b));
}

// ---------------- GEMM: C[m,n] = sum_k A[m,k] * W[n,k] (+epilogue) ----------------
// MODE 0: none (V projection)
// MODE 1: phi = elu+1  -> x>0 ? x+1 : exp(x)   (Q/K projections)
// MODE 2: + bias[n]                            (output projection)
#define BM 128
#define BN 128
#define BKK 16
#define AS_STRIDE 132   // pad to kill transposed-store bank conflicts; keeps 16B alignment

template <int MODE>
__global__ void __launch_bounds__(256, 2)
gemm_kernel(const float* __restrict__ A, const float* __restrict__ W,
            float* __restrict__ C, const float* __restrict__ bias)
{
    __shared__ float As[BKK * AS_STRIDE];
    __shared__ float Bs[BKK * AS_STRIDE];

    const int tid = threadIdx.x;
    const int tx = tid & 15;          // 16 col-groups of 8
    const int ty = tid >> 4;          // 16 row-groups of 8
    const int rowBase = blockIdx.y * BM;
    const int colBase = blockIdx.x * BN;

    unsigned long long acc[8][4];
    {
        const unsigned long long z0 = pack2(0.f, 0.f);
        #pragma unroll
        for (int i = 0; i < 8; i++)
            #pragma unroll
            for (int j = 0; j < 4; j++) acc[i][j] = z0;
    }

    const int lrow = tid >> 2;   // 0..63
    const int lc4  = tid & 3;    // which float4 of the 16-wide k-slice

    for (int kt = 0; kt < DMODEL; kt += BKK) {
        #pragma unroll
        for (int l = 0; l < 2; l++) {
            const int row = lrow + l * 64;
            const float4 va = *(const float4*)(A + (size_t)(rowBase + row) * DMODEL + kt + lc4 * 4);
            const float4 vb = *(const float4*)(W + (size_t)(colBase + row) * DMODEL + kt + lc4 * 4);
            const int kb = lc4 * 4;
            As[(kb + 0) * AS_STRIDE + row] = va.x;
            As[(kb + 1) * AS_STRIDE + row] = va.y;
            As[(kb + 2) * AS_STRIDE + row] = va.z;
            As[(kb + 3) * AS_STRIDE + row] = va.w;
            Bs[(kb + 0) * AS_STRIDE + row] = vb.x;
            Bs[(kb + 1) * AS_STRIDE + row] = vb.y;
            Bs[(kb + 2) * AS_STRIDE + row] = vb.z;
            Bs[(kb + 3) * AS_STRIDE + row] = vb.w;
        }
        __syncthreads();

        #pragma unroll
        for (int kk = 0; kk < BKK; kk++) {
            const float4 a0 = *(const float4*)(As + kk * AS_STRIDE + ty * 8);
            const float4 a1 = *(const float4*)(As + kk * AS_STRIDE + ty * 8 + 4);
            const ulonglong2 bq0 = *(const ulonglong2*)(Bs + kk * AS_STRIDE + tx * 8);
            const ulonglong2 bq1 = *(const ulonglong2*)(Bs + kk * AS_STRIDE + tx * 8 + 4);

            unsigned long long ap[8];
            ap[0] = pack2(a0.x, a0.x);
            ap[1] = pack2(a0.y, a0.y);
            ap[2] = pack2(a0.z, a0.z);
            ap[3] = pack2(a0.w, a0.w);
            ap[4] = pack2(a1.x, a1.x);
            ap[5] = pack2(a1.y, a1.y);
            ap[6] = pack2(a1.z, a1.z);
            ap[7] = pack2(a1.w, a1.w);
            unsigned long long bp[4];
            bp[0] = bq0.x; bp[1] = bq0.y; bp[2] = bq1.x; bp[3] = bq1.y;

            #pragma unroll
            for (int i = 0; i < 8; i++)
                #pragma unroll
                for (int j = 0; j < 4; j++)
                    ffma2(acc[i][j], ap[i], bp[j]);
        }
        __syncthreads();
    }

    // epilogue
    #pragma unroll
    for (int i = 0; i < 8; i++) {
        const int m = rowBase + ty * 8 + i;
        float v[8];
        #pragma unroll
        for (int j = 0; j < 4; j++) unpack2(acc[i][j], v[2 * j], v[2 * j + 1]);
        #pragma unroll
        for (int j = 0; j < 8; j++) {
            if (MODE == 1) v[j] = (v[j] > 0.f) ? (v[j] + 1.f) : __expf(v[j]);
            else if (MODE == 2) v[j] += bias[colBase + tx * 8 + j];
        }
        float4* cp = (float4*)(C + (size_t)m * DMODEL + colBase + tx * 8);
        cp[0] = make_float4(v[0], v[1], v[2], v[3]);
        cp[1] = make_float4(v[4], v[5], v[6], v[7]);
    }
}

// ---------------- KV partial: per (bh, chunk) compute sum_s K^T V over 512 s ----------------
__global__ void __launch_bounds__(256)
kv_partial_kernel()
{
    const int bh = blockIdx.x;   // 0..63
    const int ch = blockIdx.y;   // 0..7
    const int b = bh >> 4, h = bh & 15;
    const int tid = threadIdx.x;

    __shared__ float Ksh[8][DK];
    __shared__ float Vsh[8][DK];

    const int e = tid & 63;
    const int dbase = (tid >> 6) * 16;
    const int r0 = tid >> 6;   // 0..3 (load role)
    const int d0 = tid & 63;

    float acc[16];
    #pragma unroll
    for (int i = 0; i < 16; i++) acc[i] = 0.f;
    float ksum = 0.f;

    const int s0 = ch * (SEQ / NCH);
    const size_t base = ((size_t)b * SEQ + s0) * DMODEL + h * DK;

    for (int st = 0; st < SEQ / NCH; st += 8) {
        #pragma unroll
        for (int l = 0; l < 2; l++) {
            const int r = r0 + l * 4;
            const size_t g = base + (size_t)(st + r) * DMODEL + d0;
            Ksh[r][d0] = g_K[g];
            Vsh[r][d0] = g_V[g];
        }
        __syncthreads();

        #pragma unroll
        for (int r = 0; r < 8; r++) {
            const float vv = Vsh[r][e];
            const float4 k0 = *(const float4*)&Ksh[r][dbase];
            const float4 k1 = *(const float4*)&Ksh[r][dbase + 4];
            const float4 k2 = *(const float4*)&Ksh[r][dbase + 8];
            const float4 k3 = *(const float4*)&Ksh[r][dbase + 12];
            acc[0]  += k0.x * vv; acc[1]  += k0.y * vv;
            acc[2]  += k0.z * vv; acc[3]  += k0.w * vv;
            acc[4]  += k1.x * vv; acc[5]  += k1.y * vv;
            acc[6]  += k1.z * vv; acc[7]  += k1.w * vv;
            acc[8]  += k2.x * vv; acc[9]  += k2.y * vv;
            acc[10] += k2.z * vv; acc[11] += k2.w * vv;
            acc[12] += k3.x * vv; acc[13] += k3.y * vv;
            acc[14] += k3.z * vv; acc[15] += k3.w * vv;
        }
        if (tid < 64) {
            #pragma unroll
            for (int r = 0; r < 8; r++) ksum += Ksh[r][tid];
        }
        __syncthreads();
    }

    float* pkv = g_pKV + ((size_t)ch * BH + bh) * (DK * DK);
    #pragma unroll
    for (int i = 0; i < 16; i++) pkv[(dbase + i) * DK + e] = acc[i];
    if (tid < 64) g_pKsum[((size_t)ch * BH + bh) * DK + tid] = ksum;
}

// ---------------- KV reduce: sum the NCH partials (deterministic, no atomics) ----------------
__global__ void kv_reduce_kernel()
{
    const int idx = blockIdx.x * 256 + threadIdx.x;
    const int NKV = BH * DK * DK;      // 262144
    if (idx < NKV) {
        float s = 0.f;
        #pragma unroll
        for (int ch = 0; ch < NCH; ch++) s += g_pKV[(size_t)ch * NKV + idx];
        g_KV[idx] = s;
    } else if (idx < NKV + BH * DK) {
        const int o = idx - NKV;
        float s = 0.f;
        #pragma unroll
        for (int ch = 0; ch < NCH; ch++) s += g_pKsum[(size_t)ch * BH * DK + o];
        g_Ksum[o] = s;
    }
}

// ---------------- attention apply: out = (Q @ KV) / (Q . Ksum + eps) ----------------
__global__ void __launch_bounds__(256)
attn_kernel()
{
    const int bh = blockIdx.x;   // 0..63
    const int qt = blockIdx.y;   // 0..63 (tiles of 64 q rows)
    const int b = bh >> 4, h = bh & 15;
    const int tid = threadIdx.x;

    __shared__ float KVs[DK * DK];
    __shared__ float Qs[DK][DK + 1];   // [d][q], padded
    __shared__ float Ksm[DK];
    __shared__ float rden[DK];

    const size_t base = ((size_t)b * SEQ + qt * DK) * DMODEL + h * DK;

    #pragma unroll
    for (int l = 0; l < 16; l++) {
        const int idx = tid + l * 256;
        KVs[idx] = g_KV[(size_t)bh * DK * DK + idx];
        const int q = idx >> 6, d = idx & 63;
        Qs[d][q] = g_Q[base + (size_t)q * DMODEL + d];
    }
    if (tid < DK) Ksm[tid] = g_Ksum[bh * DK + tid];
    __syncthreads();

    if (tid < DK) {
        float s = 0.f;
        #pragma unroll
        for (int d = 0; d < DK; d++) s += Qs[d][tid] * Ksm[d];
        rden[tid] = 1.f / (s + 1e-6f);
    }
    __syncthreads();

    const int e = tid & 63;
    const int qg = tid >> 6;   // 0..3, each owns 16 q rows
    float acc[16];
    #pragma unroll
    for (int i = 0; i < 16; i++) acc[i] = 0.f;

    #pragma unroll 8
    for (int d = 0; d < DK; d++) {
        const float kv = KVs[d * DK + e];
        #pragma unroll
        for (int i = 0; i < 16; i++) acc[i] += Qs[d][qg * 16 + i] * kv;
    }

    #pragma unroll
    for (int i = 0; i < 16; i++) {
        const int q = qg * 16 + i;
        g_attn[base + (size_t)q * DMODEL + e] = acc[i] * rden[q];
    }
}

// ---------------- launch ----------------
extern "C" void kernel_launch(void* const* d_in, const int* in_sizes, int n_in,
                              void* d_out, int out_size)
{
    const float* query = (const float*)d_in[0];
    const float* key   = (const float*)d_in[1];
    const float* value = (const float*)d_in[2];
    const float* Wq    = (const float*)d_in[3];
    const float* Wk    = (const float*)d_in[4];
    const float* Wv    = (const float*)d_in[5];
    const float* Wo    = (const float*)d_in[6];
    const float* bo    = (const float*)d_in[7];
    float* out = (float*)d_out;
    (void)in_sizes; (void)n_in; (void)out_size;

    float *pQ, *pK, *pV, *pAttn;
    cudaGetSymbolAddress((void**)&pQ, g_Q);
    cudaGetSymbolAddress((void**)&pK, g_K);
    cudaGetSymbolAddress((void**)&pV, g_V);
    cudaGetSymbolAddress((void**)&pAttn, g_attn);

    const dim3 ggrid(DMODEL / BN, M_TOTAL / BM);   // (8, 128)

    gemm_kernel<1><<<ggrid, 256>>>(query, Wq, pQ, nullptr);   // Q = phi(q @ Wq^T)
    gemm_kernel<1><<<ggrid, 256>>>(key,   Wk, pK, nullptr);   // K = phi(k @ Wk^T)
    gemm_kernel<0><<<ggrid, 256>>>(value, Wv, pV, nullptr);   // V = v @ Wv^T

    kv_partial_kernel<<<dim3(BH, NCH), 256>>>();
    kv_reduce_kernel<<<(BH * DK * DK + BH * DK + 255) / 256, 256>>>();
    attn_kernel<<<dim3(BH, SEQ / DK), 256>>>();

    gemm_kernel<2><<<ggrid, 256>>>(pAttn, Wo, out, bo);       // out = attn @ Wo^T + bo
}

// round 3
// speedup vs baseline: 2.4285x; 2.4285x over previous
#include <cuda_runtime.h>
#include <cstdint>
#include <cstddef>

// Problem constants
#define DMODEL 1024
#define SEQ    4096
#define BATCH  4
#define NHEAD  16
#define DK     64
#define M_TOTAL (BATCH * SEQ)   // 16384
#define BH      (BATCH * NHEAD) // 64
#define NCH     8

// ---------------- scratch (static device globals; no allocation) ----------------
__device__ float g_Q[(size_t)M_TOTAL * DMODEL];
__device__ float g_K[(size_t)M_TOTAL * DMODEL];
__device__ float g_V[(size_t)M_TOTAL * DMODEL];
__device__ float g_attn[(size_t)M_TOTAL * DMODEL];
__device__ float g_pKV[(size_t)NCH * BH * DK * DK];
__device__ float g_pKsum[(size_t)NCH * BH * DK];
__device__ float g_KV[(size_t)BH * DK * DK];
__device__ float g_Ksum[(size_t)BH * DK];

// ---------------- helpers ----------------
__device__ __forceinline__ unsigned long long pack2(float x, float y) {
    unsigned long long r;
    asm("mov.b64 %0, {%1, %2};" : "=l"(r) : "f"(x), "f"(y));
    return r;
}
__device__ __forceinline__ void unpack2(unsigned long long v, float& x, float& y) {
    asm("mov.b64 {%0, %1}, %2;" : "=f"(x), "=f"(y) : "l"(v));
}
__device__ __forceinline__ void ffma2(unsigned long long& d,
                                      unsigned long long a,
                                      unsigned long long b) {
    asm("fma.rn.f32x2 %0, %1, %2, %0;" : "+l"(d) : "l"(a), "l"(b));
}
__device__ __forceinline__ uint32_t prmt7632(uint32_t a, uint32_t b) {
    uint32_t r;
    asm("prmt.b32 %0, %1, %2, 0x7632;" : "=r"(r) : "r"(a), "r"(b));
    return r;
}
__device__ __forceinline__ uint32_t smem_u32(const void* p) {
    uint32_t a;
    asm("{ .reg .u64 t; cvta.to.shared.u64 t, %1; cvt.u32.u64 %0, t; }" : "=r"(a) : "l"(p));
    return a;
}

// split float4 -> hi bf16x2 pair (truncation: exact residual) + lo bf16x2 pair (RN)
__device__ __forceinline__ void cvtsplit4(const float4& v, uint2& hi, uint2& lo) {
    const uint32_t bx = __float_as_uint(v.x), by = __float_as_uint(v.y);
    const uint32_t bz = __float_as_uint(v.z), bw = __float_as_uint(v.w);
    hi.x = prmt7632(bx, by);
    hi.y = prmt7632(bz, bw);
    const float rx = v.x - __uint_as_float(bx & 0xffff0000u);
    const float ry = v.y - __uint_as_float(by & 0xffff0000u);
    const float rz = v.z - __uint_as_float(bz & 0xffff0000u);
    const float rw = v.w - __uint_as_float(bw & 0xffff0000u);
    asm("cvt.rn.bf16x2.f32 %0, %1, %2;" : "=r"(lo.x) : "f"(ry), "f"(rx));
    asm("cvt.rn.bf16x2.f32 %0, %1, %2;" : "=r"(lo.y) : "f"(rw), "f"(rz));
}

#define LDSM_X4(r0, r1, r2, r3, addr) \
    asm volatile("ldmatrix.sync.aligned.m8n8.x4.shared.b16 {%0,%1,%2,%3}, [%4];" \
                 : "=r"(r0), "=r"(r1), "=r"(r2), "=r"(r3) : "r"(addr))

#define MMA_BF16(d, a, b0, b1) \
    asm volatile("mma.sync.aligned.m16n8k16.row.col.f32.bf16.bf16.f32 " \
                 "{%0,%1,%2,%3}, {%4,%5,%6,%7}, {%8,%9}, {%0,%1,%2,%3};" \
                 : "+f"((d)[0]), "+f"((d)[1]), "+f"((d)[2]), "+f"((d)[3]) \
                 : "r"((a)[0]), "r"((a)[1]), "r"((a)[2]), "r"((a)[3]), \
                   "r"(b0), "r"(b1))

// ---------------- HMMA GEMM: C[m,n] = sum_k A[m,k] * W[n,k] (+epilogue) ----------------
// CTA 128x128, 512 threads (16 warps, warp tile 32x32), K-stage 32, 2-slot ring.
// 3-term bf16 split: hi*hi + hi*lo + lo*hi in fp32 accumulate.
#define KSTAGE 32
#define NKIT   (DMODEL / KSTAGE)           // 32
#define ROWB   80                          // bytes per smem row (40 bf16): conflict-free ldmatrix
#define SUBT   (128 * ROWB)                // 10240 B: one 128x32 bf16 sub-tile
#define SLOT   (4 * SUBT)                  // Ahi, Alo, Bhi, Blo
#define GEMM_SMEM (2 * SLOT)               // 81920

template <int MODE>
__global__ void __launch_bounds__(512)
gemm_hmma(const float* __restrict__ A, const float* __restrict__ W,
          float* __restrict__ C, const float* __restrict__ bias)
{
    extern __shared__ char smem[];
    const uint32_t sbase = smem_u32(smem);

    const int tid  = threadIdx.x;
    const int wid  = tid >> 5;
    const int lane = tid & 31;
    const int rowBase = blockIdx.y * 128;
    const int colBase = blockIdx.x * 128;

    // warp tile: 32m x 32n; warp grid 4m x 4n
    const int wm = (wid & 3) * 32;
    const int wn = (wid >> 2) * 32;

    // ldmatrix lane address offsets (bytes within a sub-tile)
    // A: rows m (lane&15), k-octet (lane>>4)
    const uint32_t aoff = (uint32_t)(wm + (lane & 15)) * ROWB + (uint32_t)(lane >> 4) * 16;
    // B: rows n ((lane&7) + (lane>>4)*8), k-octet ((lane>>3)&1)
    const uint32_t boff = (uint32_t)(wn + (lane & 7) + ((lane >> 4) << 3)) * ROWB
                        + (uint32_t)((lane >> 3) & 1) * 16;

    // gmem staging: 2 float4 each for A and B per thread
    const int idx0 = tid;          // f4 index within 128x8
    const int idx1 = tid + 512;
    const int r0 = idx0 >> 3, c0 = idx0 & 7;
    const int r1 = idx1 >> 3, c1 = idx1 & 7;
    const float* gA0 = A + (size_t)(rowBase + r0) * DMODEL + c0 * 4;
    const float* gA1 = A + (size_t)(rowBase + r1) * DMODEL + c1 * 4;
    const float* gB0 = W + (size_t)(colBase + r0) * DMODEL + c0 * 4;
    const float* gB1 = W + (size_t)(colBase + r1) * DMODEL + c1 * 4;
    const uint32_t so0 = (uint32_t)r0 * ROWB + (uint32_t)c0 * 8;
    const uint32_t so1 = (uint32_t)r1 * ROWB + (uint32_t)c1 * 8;

    float acc[2][4][4];
#pragma unroll
    for (int i = 0; i < 2; i++)
#pragma unroll
        for (int j = 0; j < 4; j++)
#pragma unroll
            for (int r = 0; r < 4; r++) acc[i][j][r] = 0.f;

    // ---- prologue: stage 0 ----
    {
        float4 a0 = *(const float4*)gA0;
        float4 a1 = *(const float4*)gA1;
        float4 b0 = *(const float4*)gB0;
        float4 b1 = *(const float4*)gB1;
        uint2 hi, lo;
        char* s = smem;
        cvtsplit4(a0, hi, lo);
        *(uint2*)(s + so0) = hi;           *(uint2*)(s + SUBT + so0) = lo;
        cvtsplit4(a1, hi, lo);
        *(uint2*)(s + so1) = hi;           *(uint2*)(s + SUBT + so1) = lo;
        cvtsplit4(b0, hi, lo);
        *(uint2*)(s + 2 * SUBT + so0) = hi; *(uint2*)(s + 3 * SUBT + so0) = lo;
        cvtsplit4(b1, hi, lo);
        *(uint2*)(s + 2 * SUBT + so1) = hi; *(uint2*)(s + 3 * SUBT + so1) = lo;
    }
    __syncthreads();

    for (int it = 0; it < NKIT; ++it) {
        const int buf = it & 1;
        const uint32_t slot = sbase + buf * SLOT;

        // issue next-stage gmem loads early
        float4 na0, na1, nb0, nb1;
        if (it + 1 < NKIT) {
            const int kt = (it + 1) * KSTAGE;
            na0 = *(const float4*)(gA0 + kt);
            na1 = *(const float4*)(gA1 + kt);
            nb0 = *(const float4*)(gB0 + kt);
            nb1 = *(const float4*)(gB1 + kt);
        }

        // ---- compute on current buffer ----
        const uint32_t pAh = slot + aoff;
        const uint32_t pAl = slot + SUBT + aoff;
        const uint32_t pBh = slot + 2 * SUBT + boff;
        const uint32_t pBl = slot + 3 * SUBT + boff;

#pragma unroll
        for (int kk = 0; kk < 2; kk++) {
            const uint32_t ko = kk * 32;   // 16 bf16 = 32 bytes
            uint32_t ah[8], al[8], bb[8];
            LDSM_X4(ah[0], ah[1], ah[2], ah[3], pAh + ko);
            LDSM_X4(ah[4], ah[5], ah[6], ah[7], pAh + 16 * ROWB + ko);
            LDSM_X4(al[0], al[1], al[2], al[3], pAl + ko);
            LDSM_X4(al[4], al[5], al[6], al[7], pAl + 16 * ROWB + ko);
            LDSM_X4(bb[0], bb[1], bb[2], bb[3], pBh + ko);
            LDSM_X4(bb[4], bb[5], bb[6], bb[7], pBh + 16 * ROWB + ko);
#pragma unroll
            for (int mt = 0; mt < 2; mt++)
#pragma unroll
                for (int j = 0; j < 4; j++)
                    MMA_BF16(acc[mt][j], ah + mt * 4, bb[j * 2], bb[j * 2 + 1]);
#pragma unroll
            for (int mt = 0; mt < 2; mt++)
#pragma unroll
                for (int j = 0; j < 4; j++)
                    MMA_BF16(acc[mt][j], al + mt * 4, bb[j * 2], bb[j * 2 + 1]);
            LDSM_X4(bb[0], bb[1], bb[2], bb[3], pBl + ko);
            LDSM_X4(bb[4], bb[5], bb[6], bb[7], pBl + 16 * ROWB + ko);
#pragma unroll
            for (int mt = 0; mt < 2; mt++)
#pragma unroll
                for (int j = 0; j < 4; j++)
                    MMA_BF16(acc[mt][j], ah + mt * 4, bb[j * 2], bb[j * 2 + 1]);
        }

        // ---- convert+store next stage ----
        if (it + 1 < NKIT) {
            char* s = smem + (buf ^ 1) * SLOT;
            uint2 hi, lo;
            cvtsplit4(na0, hi, lo);
            *(uint2*)(s + so0) = hi;           *(uint2*)(s + SUBT + so0) = lo;
            cvtsplit4(na1, hi, lo);
            *(uint2*)(s + so1) = hi;           *(uint2*)(s + SUBT + so1) = lo;
            cvtsplit4(nb0, hi, lo);
            *(uint2*)(s + 2 * SUBT + so0) = hi; *(uint2*)(s + 3 * SUBT + so0) = lo;
            cvtsplit4(nb1, hi, lo);
            *(uint2*)(s + 2 * SUBT + so1) = hi; *(uint2*)(s + 3 * SUBT + so1) = lo;
            __syncthreads();
        }
    }

    // ---- epilogue ----
    const int lrow = lane >> 2;
    const int lcol = (lane & 3) * 2;
#pragma unroll
    for (int mt = 0; mt < 2; mt++) {
#pragma unroll
        for (int j = 0; j < 4; j++) {
            const int col = colBase + wn + j * 8 + lcol;
#pragma unroll
            for (int half = 0; half < 2; half++) {
                const int row = rowBase + wm + mt * 16 + lrow + half * 8;
                float v0 = acc[mt][j][half * 2 + 0];
                float v1 = acc[mt][j][half * 2 + 1];
                if (MODE == 1) {
                    v0 = (v0 > 0.f) ? (v0 + 1.f) : __expf(v0);
                    v1 = (v1 > 0.f) ? (v1 + 1.f) : __expf(v1);
                } else if (MODE == 2) {
                    v0 += bias[col];
                    v1 += bias[col + 1];
                }
                *(float2*)(C + (size_t)row * DMODEL + col) = make_float2(v0, v1);
            }
        }
    }
}

// ---------------- KV partial: per (bh, chunk) sum_s K^T V over 512 s ----------------
__global__ void __launch_bounds__(256)
kv_partial_kernel()
{
    const int bh = blockIdx.x;
    const int ch = blockIdx.y;
    const int b = bh >> 4, h = bh & 15;
    const int tid = threadIdx.x;

    __shared__ float Ksh[16][DK];
    __shared__ float Vsh[16][DK];

    const int e = tid & 63;
    const int dbase = (tid >> 6) * 16;

    unsigned long long acc[8];
    {
        const unsigned long long z = pack2(0.f, 0.f);
#pragma unroll
        for (int i = 0; i < 8; i++) acc[i] = z;
    }
    float ksum = 0.f;

    const int s0 = ch * (SEQ / NCH);
    const size_t base = ((size_t)b * SEQ + s0) * DMODEL + h * DK;
    const int lr = tid >> 4;
    const int lc = (tid & 15) * 4;

    for (int st = 0; st < SEQ / NCH; st += 16) {
        const size_t g = base + (size_t)(st + lr) * DMODEL + lc;
        *(float4*)&Ksh[lr][lc] = *(const float4*)(g_K + g);
        *(float4*)&Vsh[lr][lc] = *(const float4*)(g_V + g);
        __syncthreads();

#pragma unroll
        for (int r = 0; r < 16; r++) {
            const float vv = Vsh[r][e];
            const unsigned long long vvp = pack2(vv, vv);
            const ulonglong2 kA = *(const ulonglong2*)&Ksh[r][dbase];
            const ulonglong2 kB = *(const ulonglong2*)&Ksh[r][dbase + 4];
            const ulonglong2 kC = *(const ulonglong2*)&Ksh[r][dbase + 8];
            const ulonglong2 kD = *(const ulonglong2*)&Ksh[r][dbase + 12];
            ffma2(acc[0], kA.x, vvp); ffma2(acc[1], kA.y, vvp);
            ffma2(acc[2], kB.x, vvp); ffma2(acc[3], kB.y, vvp);
            ffma2(acc[4], kC.x, vvp); ffma2(acc[5], kC.y, vvp);
            ffma2(acc[6], kD.x, vvp); ffma2(acc[7], kD.y, vvp);
        }
        if (tid < 64) {
#pragma unroll
            for (int r = 0; r < 16; r++) ksum += Ksh[r][tid];
        }
        __syncthreads();
    }

    float* pkv = g_pKV + ((size_t)ch * BH + bh) * (DK * DK);
#pragma unroll
    for (int p = 0; p < 8; p++) {
        float v0, v1;
        unpack2(acc[p], v0, v1);
        pkv[(dbase + 2 * p) * DK + e] = v0;
        pkv[(dbase + 2 * p + 1) * DK + e] = v1;
    }
    if (tid < 64) g_pKsum[((size_t)ch * BH + bh) * DK + tid] = ksum;
}

// ---------------- KV reduce ----------------
__global__ void kv_reduce_kernel()
{
    const int idx = blockIdx.x * 256 + threadIdx.x;
    const int NKV = BH * DK * DK;
    if (idx < NKV) {
        float s = 0.f;
#pragma unroll
        for (int ch = 0; ch < NCH; ch++) s += g_pKV[(size_t)ch * NKV + idx];
        g_KV[idx] = s;
    } else if (idx < NKV + BH * DK) {
        const int o = idx - NKV;
        float s = 0.f;
#pragma unroll
        for (int ch = 0; ch < NCH; ch++) s += g_pKsum[(size_t)ch * BH * DK + o];
        g_Ksum[o] = s;
    }
}

// ---------------- attention apply: out = (Q @ KV) / (Q . Ksum + eps) ----------------
__global__ void __launch_bounds__(256)
attn_kernel()
{
    const int bh = blockIdx.x;
    const int qt = blockIdx.y;
    const int b = bh >> 4, h = bh & 15;
    const int tid = threadIdx.x;

    __shared__ float KVs[DK * DK];
    __shared__ float Qs[DK][DK + 2];
    __shared__ float Ksm[DK];
    __shared__ float rden[DK];

    const size_t base = ((size_t)b * SEQ + qt * DK) * DMODEL + h * DK;

#pragma unroll
    for (int l = 0; l < 16; l++) {
        const int idx = tid + l * 256;
        KVs[idx] = g_KV[(size_t)bh * DK * DK + idx];
        const int q = idx >> 6, d = idx & 63;
        Qs[d][q] = g_Q[base + (size_t)q * DMODEL + d];
    }
    if (tid < DK) Ksm[tid] = g_Ksum[bh * DK + tid];
    __syncthreads();

    if (tid < DK) {
        float s = 0.f;
#pragma unroll
        for (int d = 0; d < DK; d++) s += Qs[d][tid] * Ksm[d];
        rden[tid] = 1.f / (s + 1e-6f);
    }
    __syncthreads();

    const int e = tid & 63;
    const int qg = tid >> 6;

    unsigned long long acc[8];
    {
        const unsigned long long z = pack2(0.f, 0.f);
#pragma unroll
        for (int i = 0; i < 8; i++) acc[i] = z;
    }

#pragma unroll 8
    for (int d = 0; d < DK; d++) {
        const float kv = KVs[d * DK + e];
        const unsigned long long kvp = pack2(kv, kv);
#pragma unroll
        for (int t = 0; t < 8; t++) {
            const unsigned long long qp =
                *(const unsigned long long*)&Qs[d][qg * 16 + 2 * t];
            ffma2(acc[t], qp, kvp);
        }
    }

#pragma unroll
    for (int t = 0; t < 8; t++) {
        float v0, v1;
        unpack2(acc[t], v0, v1);
        const int q0 = qg * 16 + 2 * t;
        g_attn[base + (size_t)q0 * DMODEL + e] = v0 * rden[q0];
        g_attn[base + (size_t)(q0 + 1) * DMODEL + e] = v1 * rden[q0 + 1];
    }
}

// ---------------- launch ----------------
extern "C" void kernel_launch(void* const* d_in, const int* in_sizes, int n_in,
                              void* d_out, int out_size)
{
    const float* query = (const float*)d_in[0];
    const float* key   = (const float*)d_in[1];
    const float* value = (const float*)d_in[2];
    const float* Wq    = (const float*)d_in[3];
    const float* Wk    = (const float*)d_in[4];
    const float* Wv    = (const float*)d_in[5];
    const float* Wo    = (const float*)d_in[6];
    const float* bo    = (const float*)d_in[7];
    float* out = (float*)d_out;
    (void)in_sizes; (void)n_in; (void)out_size;

    float *pQ, *pK, *pV, *pAttn;
    cudaGetSymbolAddress((void**)&pQ, g_Q);
    cudaGetSymbolAddress((void**)&pK, g_K);
    cudaGetSymbolAddress((void**)&pV, g_V);
    cudaGetSymbolAddress((void**)&pAttn, g_attn);

    cudaFuncSetAttribute(gemm_hmma<0>, cudaFuncAttributeMaxDynamicSharedMemorySize, GEMM_SMEM);
    cudaFuncSetAttribute(gemm_hmma<1>, cudaFuncAttributeMaxDynamicSharedMemorySize, GEMM_SMEM);
    cudaFuncSetAttribute(gemm_hmma<2>, cudaFuncAttributeMaxDynamicSharedMemorySize, GEMM_SMEM);

    const dim3 ggrid(DMODEL / 128, M_TOTAL / 128);   // (8, 128)

    gemm_hmma<1><<<ggrid, 512, GEMM_SMEM>>>(query, Wq, pQ, nullptr);
    gemm_hmma<1><<<ggrid, 512, GEMM_SMEM>>>(key,   Wk, pK, nullptr);
    gemm_hmma<0><<<ggrid, 512, GEMM_SMEM>>>(value, Wv, pV, nullptr);

    kv_partial_kernel<<<dim3(BH, NCH), 256>>>();
    kv_reduce_kernel<<<(BH * DK * DK + BH * DK + 255) / 256, 256>>>();
    attn_kernel<<<dim3(BH, SEQ / DK), 256>>>();

    gemm_hmma<2><<<ggrid, 512, GEMM_SMEM>>>(pAttn, Wo, out, bo);
}